// round 2
// baseline (speedup 1.0000x reference)
#include <cuda_runtime.h>

#define NN 100000
#define EE 500000
#define MM 2
#define DD 64
#define HH 128
#define BB 8192

// ---------------- scratch (static __device__ per allocation rules) ----------
// ntype-major: index = ((t*MM + m)*NN + n)
__device__ float    g_feat[2 * MM * NN * DD];   // transformed features
__device__ float    g_z[2 * MM * NN * DD];      // accumulator, then elu'd z
__device__ float    g_el[2 * MM * NN];
__device__ float    g_er[2 * MM * NN];
__device__ unsigned g_mx[2 * MM * NN];          // encoded segment max
__device__ float    g_den[2 * MM * NN];         // softmax denominators
__device__ float    g_edge[2 * MM * EE];        // e values, then exp values
__device__ float    g_embU[NN * DD];
__device__ float    g_embI[NN * DD];
__device__ float    g_wsum[2 * MM];
__device__ float    g_beta[2 * MM];

// order-preserving float <-> uint encoding for atomicMax over signed floats
__device__ __forceinline__ unsigned encf(float f) {
    unsigned u = __float_as_uint(f);
    return (u & 0x80000000u) ? ~u : (u | 0x80000000u);
}
__device__ __forceinline__ float decf(unsigned u) {
    return (u & 0x80000000u) ? __uint_as_float(u & 0x7FFFFFFFu)
                             : __uint_as_float(~u);
}

// ---------------- stage 1: feat = h @ W[m]; el, er; init accumulators -------
// grid: (ceil(N/8), MM, 2)   block: 256
__global__ void k_transform(const float* __restrict__ hU, const float* __restrict__ hI,
                            const float* __restrict__ WU, const float* __restrict__ WI,
                            const float* __restrict__ alU, const float* __restrict__ alI,
                            const float* __restrict__ arU, const float* __restrict__ arI,
                            int N)
{
    __shared__ float Ws[DD * DD];
    __shared__ float als[DD], ars[DD];
    const int t   = blockIdx.z;
    const int m   = blockIdx.y;
    const int tid = threadIdx.x;
    const float* h  = t ? hI  : hU;
    const float* W  = t ? WI  : WU;
    const float* al = t ? alI : alU;
    const float* ar = t ? arI : arU;
    for (int i = tid; i < DD * DD; i += blockDim.x) Ws[i] = W[m * DD * DD + i];
    if (tid < DD) { als[tid] = al[m * DD + tid]; ars[tid] = ar[m * DD + tid]; }
    if (blockIdx.x == 0 && m == 0 && tid < MM) g_wsum[t * MM + tid] = 0.0f;
    __syncthreads();

    const int warp = tid >> 5, lane = tid & 31;
    const int n = blockIdx.x * 8 + warp;
    if (n >= N) return;

    float hr0 = h[n * DD + lane];
    float hr1 = h[n * DD + 32 + lane];
    float a0 = 0.0f, a1 = 0.0f;
#pragma unroll
    for (int k = 0; k < 32; k++) {
        float hk = __shfl_sync(0xffffffffu, hr0, k);
        a0 = fmaf(hk, Ws[k * DD + lane], a0);
        a1 = fmaf(hk, Ws[k * DD + 32 + lane], a1);
    }
#pragma unroll
    for (int k = 0; k < 32; k++) {
        float hk = __shfl_sync(0xffffffffu, hr1, k);
        a0 = fmaf(hk, Ws[(k + 32) * DD + lane], a0);
        a1 = fmaf(hk, Ws[(k + 32) * DD + 32 + lane], a1);
    }
    const size_t nb   = (size_t)(t * MM + m) * N + n;
    const size_t base = nb * DD;
    g_feat[base + lane]      = a0;
    g_feat[base + 32 + lane] = a1;
    g_z[base + lane]      = 0.0f;      // zero accumulator for scatter
    g_z[base + 32 + lane] = 0.0f;

    float pe = a0 * als[lane] + a1 * als[32 + lane];
    float pr = a0 * ars[lane] + a1 * ars[32 + lane];
#pragma unroll
    for (int o = 16; o > 0; o >>= 1) {
        pe += __shfl_xor_sync(0xffffffffu, pe, o);
        pr += __shfl_xor_sync(0xffffffffu, pr, o);
    }
    if (lane == 0) {
        g_el[nb] = pe;
        g_er[nb] = pr;
        g_mx[nb]  = 0u;      // encodes below any finite float
        g_den[nb] = 0.0f;
    }
}

// ---------------- stage 2: edge logits + segment max ------------------------
// grid: (ceil(E/256), MM, 2)
__global__ void k_edge_max(const int* __restrict__ srcU, const int* __restrict__ dstU,
                           const int* __restrict__ srcI, const int* __restrict__ dstI,
                           int N)
{
    const int t = blockIdx.z;
    const int m = blockIdx.y;
    const int e = blockIdx.x * blockDim.x + threadIdx.x;
    if (e >= EE) return;
    const int* src = t ? srcI : srcU;
    const int* dst = t ? dstI : dstU;
    const int s = src[m * EE + e];
    const int d = dst[m * EE + e];
    const size_t nbase = (size_t)(t * MM + m) * N;
    float v = g_el[nbase + s] + g_er[nbase + d];
    v = (v > 0.0f) ? v : 0.2f * v;   // leaky relu, slope 0.2
    g_edge[(size_t)(t * MM + m) * EE + e] = v;
    atomicMax(&g_mx[nbase + d], encf(v));
}

// ---------------- stage 3: exp + denominator --------------------------------
__global__ void k_edge_exp(const int* __restrict__ dstU, const int* __restrict__ dstI,
                           int N)
{
    const int t = blockIdx.z;
    const int m = blockIdx.y;
    const int e = blockIdx.x * blockDim.x + threadIdx.x;
    if (e >= EE) return;
    const int* dst = t ? dstI : dstU;
    const int d = dst[m * EE + e];
    const size_t nbase = (size_t)(t * MM + m) * N;
    const size_t eidx  = (size_t)(t * MM + m) * EE + e;
    float mx = decf(g_mx[nbase + d]);
    float ex = expf(g_edge[eidx] - mx);
    g_edge[eidx] = ex;
    atomicAdd(&g_den[nbase + d], ex);
}

// ---------------- stage 4: alpha * feat[src] -> z[dst] (vector red) ---------
// grid: (ceil(E*16/256), MM, 2); 16 threads per edge, float4 each
__global__ void k_scatter(const int* __restrict__ srcU, const int* __restrict__ dstU,
                          const int* __restrict__ srcI, const int* __restrict__ dstI,
                          int N)
{
    const int t   = blockIdx.z;
    const int m   = blockIdx.y;
    const int idx = blockIdx.x * blockDim.x + threadIdx.x;
    const int e = idx >> 4;
    const int g = idx & 15;
    if (e >= EE) return;
    const int* src = t ? srcI : srcU;
    const int* dst = t ? dstI : dstU;
    const int s = src[m * EE + e];
    const int d = dst[m * EE + e];
    const size_t nbase = (size_t)(t * MM + m) * N;
    const float alpha = g_edge[(size_t)(t * MM + m) * EE + e]
                      / (g_den[nbase + d] + 1e-9f);
    const float4* f4 = (const float4*)&g_feat[(nbase + s) * DD];
    float4 v = f4[g];
    v.x *= alpha; v.y *= alpha; v.z *= alpha; v.w *= alpha;
    float* p = &g_z[(nbase + d) * DD + g * 4];
    asm volatile("red.global.add.v4.f32 [%0], {%1,%2,%3,%4};"
                 :: "l"(p), "f"(v.x), "f"(v.y), "f"(v.z), "f"(v.w) : "memory");
}

// ---------------- stage 5: z = elu(acc + b); semantic score accumulation ----
// grid: (ceil(N/8), MM, 2)
__global__ void k_finalize(const float* __restrict__ bU, const float* __restrict__ bI,
                           const float* __restrict__ W1U, const float* __restrict__ W1I,
                           const float* __restrict__ b1U, const float* __restrict__ b1I,
                           const float* __restrict__ W2U, const float* __restrict__ W2I,
                           int N)
{
    __shared__ float W1s[DD * HH];
    __shared__ float b1s[HH], W2s[HH], bs[DD];
    __shared__ float part[8];
    const int t   = blockIdx.z;
    const int m   = blockIdx.y;
    const int tid = threadIdx.x;
    const float* b  = t ? bI  : bU;
    const float* W1 = t ? W1I : W1U;
    const float* b1 = t ? b1I : b1U;
    const float* W2 = t ? W2I : W2U;
    for (int i = tid; i < DD * HH; i += blockDim.x) W1s[i] = W1[i];
    if (tid < HH) { b1s[tid] = b1[tid]; W2s[tid] = W2[tid]; }
    if (tid < DD) bs[tid] = b[m * DD + tid];
    __syncthreads();

    const int warp = tid >> 5, lane = tid & 31;
    const int n = blockIdx.x * 8 + warp;
    float sval = 0.0f;
    if (n < N) {
        const size_t base = ((size_t)(t * MM + m) * N + n) * DD;
        float z0 = g_z[base + lane]      + bs[lane];
        float z1 = g_z[base + 32 + lane] + bs[32 + lane];
        z0 = (z0 > 0.0f) ? z0 : expm1f(z0);   // elu, alpha=1
        z1 = (z1 > 0.0f) ? z1 : expm1f(z1);
        g_z[base + lane]      = z0;
        g_z[base + 32 + lane] = z1;

        float acc[4];
#pragma unroll
        for (int j = 0; j < 4; j++) acc[j] = b1s[lane + 32 * j];
#pragma unroll
        for (int k = 0; k < 32; k++) {
            float zk = __shfl_sync(0xffffffffu, z0, k);
#pragma unroll
            for (int j = 0; j < 4; j++)
                acc[j] = fmaf(zk, W1s[k * HH + lane + 32 * j], acc[j]);
        }
#pragma unroll
        for (int k = 0; k < 32; k++) {
            float zk = __shfl_sync(0xffffffffu, z1, k);
#pragma unroll
            for (int j = 0; j < 4; j++)
                acc[j] = fmaf(zk, W1s[(k + 32) * HH + lane + 32 * j], acc[j]);
        }
#pragma unroll
        for (int j = 0; j < 4; j++) sval += tanhf(acc[j]) * W2s[lane + 32 * j];
#pragma unroll
        for (int o = 16; o > 0; o >>= 1) sval += __shfl_xor_sync(0xffffffffu, sval, o);
    }
    if (lane == 0) part[warp] = (n < N) ? sval : 0.0f;
    __syncthreads();
    if (tid == 0) {
        float v = 0.0f;
#pragma unroll
        for (int w = 0; w < 8; w++) v += part[w];
        atomicAdd(&g_wsum[t * MM + m], v);
    }
}

// ---------------- stage 6: beta = softmax over metapaths (both ntypes) ------
__global__ void k_beta(int N)
{
#pragma unroll
    for (int t = 0; t < 2; t++) {
        float w0 = g_wsum[t * MM + 0] / (float)N;
        float w1 = g_wsum[t * MM + 1] / (float)N;
        float mx = fmaxf(w0, w1);
        float e0 = expf(w0 - mx), e1 = expf(w1 - mx);
        float s = e0 + e1;
        g_beta[t * MM + 0] = e0 / s;
        g_beta[t * MM + 1] = e1 / s;
    }
}

// ---------------- stage 7: combine + project + relu + layernorm -------------
// grid: (ceil(N/8), 2)
__global__ void k_project(const float* __restrict__ WpU, const float* __restrict__ bpU,
                          const float* __restrict__ WpI, const float* __restrict__ bpI,
                          const float* __restrict__ gln, const float* __restrict__ bln,
                          int N)
{
    __shared__ float Ws[DD * DD];
    __shared__ float bps[DD], gs[DD], bls[DD];
    __shared__ float bet[2];
    const int t   = blockIdx.y;
    const int tid = threadIdx.x;
    const float* Wp = t ? WpI : WpU;
    const float* bp = t ? bpI : bpU;
    for (int i = tid; i < DD * DD; i += blockDim.x) Ws[i] = Wp[i];
    if (tid < DD) { bps[tid] = bp[tid]; gs[tid] = gln[tid]; bls[tid] = bln[tid]; }
    if (tid < 2) bet[tid] = g_beta[t * MM + tid];
    __syncthreads();

    const int warp = tid >> 5, lane = tid & 31;
    const int n = blockIdx.x * 8 + warp;
    if (n >= N) return;

    const size_t b0 = ((size_t)(t * MM + 0) * N + n) * DD;
    const size_t b1 = ((size_t)(t * MM + 1) * N + n) * DD;
    float c0 = bet[0] * g_z[b0 + lane]      + bet[1] * g_z[b1 + lane];
    float c1 = bet[0] * g_z[b0 + 32 + lane] + bet[1] * g_z[b1 + 32 + lane];

    float a0 = bps[lane], a1 = bps[32 + lane];
#pragma unroll
    for (int k = 0; k < 32; k++) {
        float ck = __shfl_sync(0xffffffffu, c0, k);
        a0 = fmaf(ck, Ws[k * DD + lane], a0);
        a1 = fmaf(ck, Ws[k * DD + 32 + lane], a1);
    }
#pragma unroll
    for (int k = 0; k < 32; k++) {
        float ck = __shfl_sync(0xffffffffu, c1, k);
        a0 = fmaf(ck, Ws[(k + 32) * DD + lane], a0);
        a1 = fmaf(ck, Ws[(k + 32) * DD + 32 + lane], a1);
    }
    a0 = fmaxf(a0, 0.0f);
    a1 = fmaxf(a1, 0.0f);

    float s = a0 + a1;
#pragma unroll
    for (int o = 16; o > 0; o >>= 1) s += __shfl_xor_sync(0xffffffffu, s, o);
    float mu = s * (1.0f / DD);
    float d0 = a0 - mu, d1 = a1 - mu;
    float v = d0 * d0 + d1 * d1;
#pragma unroll
    for (int o = 16; o > 0; o >>= 1) v += __shfl_xor_sync(0xffffffffu, v, o);
    float inv = rsqrtf(v * (1.0f / DD) + 1e-5f);

    float* emb = t ? g_embI : g_embU;
    emb[(size_t)n * DD + lane]      = gs[lane]      * d0 * inv + bls[lane];
    emb[(size_t)n * DD + 32 + lane] = gs[32 + lane] * d1 * inv + bls[32 + lane];
}

// ---------------- stage 8: gather outputs -----------------------------------
__global__ void k_gather(const int* __restrict__ ui, const int* __restrict__ ii,
                         const int* __restrict__ ni, float* __restrict__ out)
{
    const int idx = blockIdx.x * blockDim.x + threadIdx.x;
    const int r = idx >> 4, g = idx & 15;
    if (r >= 3 * BB) return;
    const float* srcp;
    if (r < BB)            srcp = &g_embU[(size_t)ui[r] * DD];
    else if (r < 2 * BB)   srcp = &g_embI[(size_t)ii[r - BB] * DD];
    else                   srcp = &g_embI[(size_t)ni[r - 2 * BB] * DD];
    ((float4*)out)[(size_t)r * 16 + g] = ((const float4*)srcp)[g];
}

// ---------------- launch -----------------------------------------------------
extern "C" void kernel_launch(void* const* d_in, const int* in_sizes, int n_in,
                              void* d_out, int out_size)
{
    const int*   user_idx  = (const int*)  d_in[0];
    const int*   item_idx  = (const int*)  d_in[1];
    const int*   neg_idx   = (const int*)  d_in[2];
    const float* user_feat = (const float*)d_in[3];
    const float* item_feat = (const float*)d_in[4];
    const int*   u_src = (const int*)d_in[5];
    const int*   u_dst = (const int*)d_in[6];
    const int*   i_src = (const int*)d_in[7];
    const int*   i_dst = (const int*)d_in[8];
    const float* u_W  = (const float*)d_in[9];
    const float* u_al = (const float*)d_in[10];
    const float* u_ar = (const float*)d_in[11];
    const float* u_b  = (const float*)d_in[12];
    const float* i_W  = (const float*)d_in[13];
    const float* i_al = (const float*)d_in[14];
    const float* i_ar = (const float*)d_in[15];
    const float* i_b  = (const float*)d_in[16];
    const float* u_saW1 = (const float*)d_in[17];
    const float* u_sab1 = (const float*)d_in[18];
    const float* u_saW2 = (const float*)d_in[19];
    const float* i_saW1 = (const float*)d_in[20];
    const float* i_sab1 = (const float*)d_in[21];
    const float* i_saW2 = (const float*)d_in[22];
    const float* userW = (const float*)d_in[23];
    const float* userb = (const float*)d_in[24];
    const float* itemW = (const float*)d_in[25];
    const float* itemb = (const float*)d_in[26];
    const float* ln_g  = (const float*)d_in[27];
    const float* ln_b  = (const float*)d_in[28];
    float* out = (float*)d_out;

    const dim3 blk(256);
    const dim3 gNode((NN + 7) / 8, MM, 2);
    const dim3 gEdge((EE + 255) / 256, MM, 2);
    const dim3 gScat((EE * 16 + 255) / 256, MM, 2);
    const dim3 gProj((NN + 7) / 8, 2);

    k_transform<<<gNode, blk>>>(user_feat, item_feat, u_W, i_W,
                                u_al, i_al, u_ar, i_ar, NN);
    k_edge_max<<<gEdge, blk>>>(u_src, u_dst, i_src, i_dst, NN);
    k_edge_exp<<<gEdge, blk>>>(u_dst, i_dst, NN);
    k_scatter<<<gScat, blk>>>(u_src, u_dst, i_src, i_dst, NN);
    k_finalize<<<gNode, blk>>>(u_b, i_b, u_saW1, i_saW1,
                               u_sab1, i_sab1, u_saW2, i_saW2, NN);
    k_beta<<<1, 1>>>(NN);
    k_project<<<gProj, blk>>>(userW, userb, itemW, itemb, ln_g, ln_b, NN);
    k_gather<<<(3 * BB * 16 + 255) / 256, blk>>>(user_idx, item_idx, neg_idx, out);
}

// round 14
// speedup vs baseline: 3.0148x; 3.0148x over previous
#include <cuda_runtime.h>

#define NN 100000
#define EE 500000
#define MM 2
#define DD 64
#define HH 128
#define BB 8192

// ---------------- scratch (static __device__ per allocation rules) ----------
// ntype-major: index = ((t*MM + m)*NN + n)
__device__ float g_feat[2 * MM * NN * DD];   // transformed features
__device__ float g_z[2 * MM * NN * DD];      // accumulator, then elu'd z
__device__ float g_el[2 * MM * NN];
__device__ float g_er[2 * MM * NN];
__device__ float g_den[2 * MM * NN];         // softmax denominators
__device__ float g_edge[2 * MM * EE];        // exp(e) values
__device__ float g_embU[NN * DD];
__device__ float g_embI[NN * DD];
__device__ float g_wsum[2 * MM];
__device__ float g_beta[2 * MM];

__device__ __forceinline__ float tanh_fast(float x) {
    float y;
    asm("tanh.approx.f32 %0, %1;" : "=f"(y) : "f"(x));
    return y;
}

// ---------------- stage 1: feat = h @ W[m]; el, er; init accumulators -------
// grid: (N/32, MM, 2)  block: 256  (8 warps x 4 nodes = 32 nodes/block)
__global__ void k_transform(const float* __restrict__ hU, const float* __restrict__ hI,
                            const float* __restrict__ WU, const float* __restrict__ WI,
                            const float* __restrict__ alU, const float* __restrict__ alI,
                            const float* __restrict__ arU, const float* __restrict__ arI,
                            int N)
{
    __shared__ float Ws[DD * DD];
    __shared__ float als[DD], ars[DD];
    const int t   = blockIdx.z;
    const int m   = blockIdx.y;
    const int tid = threadIdx.x;
    const float* h  = t ? hI  : hU;
    const float* W  = t ? WI  : WU;
    const float* al = t ? alI : alU;
    const float* ar = t ? arI : arU;
    for (int i = tid; i < DD * DD; i += blockDim.x) Ws[i] = W[m * DD * DD + i];
    if (tid < DD) { als[tid] = al[m * DD + tid]; ars[tid] = ar[m * DD + tid]; }
    if (blockIdx.x == 0 && m == 0 && tid < MM) g_wsum[t * MM + tid] = 0.0f;
    __syncthreads();

    const int warp = tid >> 5, lane = tid & 31;
    const int n0 = (blockIdx.x * 8 + warp) * 4;          // 4 nodes per warp
    if (n0 >= N) return;

    float hr0[4], hr1[4], a0[4], a1[4];
#pragma unroll
    for (int j = 0; j < 4; j++) {
        hr0[j] = h[(n0 + j) * DD + lane];
        hr1[j] = h[(n0 + j) * DD + 32 + lane];
        a0[j] = 0.0f; a1[j] = 0.0f;
    }
#pragma unroll
    for (int k = 0; k < 32; k++) {
        const float w0 = Ws[k * DD + lane];
        const float w1 = Ws[k * DD + 32 + lane];
#pragma unroll
        for (int j = 0; j < 4; j++) {
            float hk = __shfl_sync(0xffffffffu, hr0[j], k);
            a0[j] = fmaf(hk, w0, a0[j]);
            a1[j] = fmaf(hk, w1, a1[j]);
        }
    }
#pragma unroll
    for (int k = 0; k < 32; k++) {
        const float w0 = Ws[(k + 32) * DD + lane];
        const float w1 = Ws[(k + 32) * DD + 32 + lane];
#pragma unroll
        for (int j = 0; j < 4; j++) {
            float hk = __shfl_sync(0xffffffffu, hr1[j], k);
            a0[j] = fmaf(hk, w0, a0[j]);
            a1[j] = fmaf(hk, w1, a1[j]);
        }
    }
    const size_t nbase = (size_t)(t * MM + m) * N;
    float pe[4], pr[4];
#pragma unroll
    for (int j = 0; j < 4; j++) {
        const size_t base = (nbase + n0 + j) * DD;
        g_feat[base + lane]      = a0[j];
        g_feat[base + 32 + lane] = a1[j];
        g_z[base + lane]      = 0.0f;
        g_z[base + 32 + lane] = 0.0f;
        pe[j] = a0[j] * als[lane] + a1[j] * als[32 + lane];
        pr[j] = a0[j] * ars[lane] + a1[j] * ars[32 + lane];
#pragma unroll
        for (int o = 16; o > 0; o >>= 1) {
            pe[j] += __shfl_xor_sync(0xffffffffu, pe[j], o);
            pr[j] += __shfl_xor_sync(0xffffffffu, pr[j], o);
        }
    }
    if (lane == 0) {
#pragma unroll
        for (int j = 0; j < 4; j++) {
            g_el[nbase + n0 + j]  = pe[j];
            g_er[nbase + n0 + j]  = pr[j];
            g_den[nbase + n0 + j] = 0.0f;
        }
    }
}

// ---------------- stage 2: fused edge logit + exp + denominator -------------
// (no max subtraction: |logit| bounded << 80, exp() cannot overflow; softmax
//  is shift-invariant so the result is mathematically identical)
// grid: (ceil(E/256), MM, 2)
__global__ void k_edge(const int* __restrict__ srcU, const int* __restrict__ dstU,
                       const int* __restrict__ srcI, const int* __restrict__ dstI,
                       int N)
{
    const int t = blockIdx.z;
    const int m = blockIdx.y;
    const int e = blockIdx.x * blockDim.x + threadIdx.x;
    if (e >= EE) return;
    const int* src = t ? srcI : srcU;
    const int* dst = t ? dstI : dstU;
    const int s = src[m * EE + e];
    const int d = dst[m * EE + e];
    const size_t nbase = (size_t)(t * MM + m) * N;
    float v = g_el[nbase + s] + g_er[nbase + d];
    v = (v > 0.0f) ? v : 0.2f * v;   // leaky relu, slope 0.2
    float ex = __expf(v);
    g_edge[(size_t)(t * MM + m) * EE + e] = ex;
    atomicAdd(&g_den[nbase + d], ex);
}

// ---------------- stage 3: alpha * feat[src] -> z[dst] (vector red) ---------
// grid: (E*16/256, MM, 2); 16 threads per edge, scalars loaded once per group
__global__ void k_scatter(const int* __restrict__ srcU, const int* __restrict__ dstU,
                          const int* __restrict__ srcI, const int* __restrict__ dstI,
                          int N)
{
    const int t   = blockIdx.z;
    const int m   = blockIdx.y;
    const int idx = blockIdx.x * blockDim.x + threadIdx.x;
    const int e = idx >> 4;
    const int g = idx & 15;
    if (e >= EE) return;
    const int lane = threadIdx.x & 31;
    const int lead = lane & 16;                      // leader lane of 16-group
    const unsigned mask = 0xFFFFu << lead;

    const size_t nbase = (size_t)(t * MM + m) * N;
    int s = 0, d = 0;
    float alpha = 0.0f;
    if (g == 0) {
        const int* src = t ? srcI : srcU;
        const int* dst = t ? dstI : dstU;
        s = src[m * EE + e];
        d = dst[m * EE + e];
        alpha = g_edge[(size_t)(t * MM + m) * EE + e]
              / (g_den[nbase + d] + 1e-9f);
    }
    s     = __shfl_sync(mask, s, lead);
    d     = __shfl_sync(mask, d, lead);
    alpha = __shfl_sync(mask, alpha, lead);

    const float4* f4 = (const float4*)&g_feat[(nbase + s) * DD];
    float4 v = f4[g];
    v.x *= alpha; v.y *= alpha; v.z *= alpha; v.w *= alpha;
    float* p = &g_z[(nbase + d) * DD + g * 4];
    asm volatile("red.global.add.v4.f32 [%0], {%1,%2,%3,%4};"
                 :: "l"(p), "f"(v.x), "f"(v.y), "f"(v.z), "f"(v.w) : "memory");
}

// ---------------- stage 4: z = elu(acc + b); semantic score accumulation ----
// grid: (N/32, MM, 2)  block: 256  (4 nodes per warp)
__global__ void k_finalize(const float* __restrict__ bU, const float* __restrict__ bI,
                           const float* __restrict__ W1U, const float* __restrict__ W1I,
                           const float* __restrict__ b1U, const float* __restrict__ b1I,
                           const float* __restrict__ W2U, const float* __restrict__ W2I,
                           int N)
{
    __shared__ float W1s[DD * HH];
    __shared__ float b1s[HH], W2s[HH], bs[DD];
    __shared__ float part[8];
    const int t   = blockIdx.z;
    const int m   = blockIdx.y;
    const int tid = threadIdx.x;
    const float* b  = t ? bI  : bU;
    const float* W1 = t ? W1I : W1U;
    const float* b1 = t ? b1I : b1U;
    const float* W2 = t ? W2I : W2U;
    for (int i = tid; i < DD * HH; i += blockDim.x) W1s[i] = W1[i];
    if (tid < HH) { b1s[tid] = b1[tid]; W2s[tid] = W2[tid]; }
    if (tid < DD) bs[tid] = b[m * DD + tid];
    __syncthreads();

    const int warp = tid >> 5, lane = tid & 31;
    const int n0 = (blockIdx.x * 8 + warp) * 4;
    float sval = 0.0f;
    if (n0 < N) {
        const size_t nbase = (size_t)(t * MM + m) * N;
        float z0[4], z1[4];
#pragma unroll
        for (int j = 0; j < 4; j++) {
            const size_t base = (nbase + n0 + j) * DD;
            float u0 = g_z[base + lane]      + bs[lane];
            float u1 = g_z[base + 32 + lane] + bs[32 + lane];
            u0 = (u0 > 0.0f) ? u0 : expm1f(u0);   // elu, alpha=1
            u1 = (u1 > 0.0f) ? u1 : expm1f(u1);
            g_z[base + lane]      = u0;
            g_z[base + 32 + lane] = u1;
            z0[j] = u0; z1[j] = u1;
        }
        float acc[4][4];
#pragma unroll
        for (int j = 0; j < 4; j++)
#pragma unroll
            for (int c = 0; c < 4; c++) acc[j][c] = b1s[lane + 32 * c];
#pragma unroll
        for (int k = 0; k < 32; k++) {
            float w[4];
#pragma unroll
            for (int c = 0; c < 4; c++) w[c] = W1s[k * HH + lane + 32 * c];
#pragma unroll
            for (int j = 0; j < 4; j++) {
                float zk = __shfl_sync(0xffffffffu, z0[j], k);
#pragma unroll
                for (int c = 0; c < 4; c++) acc[j][c] = fmaf(zk, w[c], acc[j][c]);
            }
        }
#pragma unroll
        for (int k = 0; k < 32; k++) {
            float w[4];
#pragma unroll
            for (int c = 0; c < 4; c++) w[c] = W1s[(k + 32) * HH + lane + 32 * c];
#pragma unroll
            for (int j = 0; j < 4; j++) {
                float zk = __shfl_sync(0xffffffffu, z1[j], k);
#pragma unroll
                for (int c = 0; c < 4; c++) acc[j][c] = fmaf(zk, w[c], acc[j][c]);
            }
        }
        // only the SUM over nodes of the per-node score is needed downstream
#pragma unroll
        for (int j = 0; j < 4; j++)
#pragma unroll
            for (int c = 0; c < 4; c++)
                sval += tanh_fast(acc[j][c]) * W2s[lane + 32 * c];
#pragma unroll
        for (int o = 16; o > 0; o >>= 1) sval += __shfl_xor_sync(0xffffffffu, sval, o);
    }
    if (lane == 0) part[warp] = (n0 < N) ? sval : 0.0f;
    __syncthreads();
    if (tid == 0) {
        float v = 0.0f;
#pragma unroll
        for (int w = 0; w < 8; w++) v += part[w];
        atomicAdd(&g_wsum[t * MM + m], v);
    }
}

// ---------------- stage 5: beta = softmax over metapaths (both ntypes) ------
__global__ void k_beta(int N)
{
#pragma unroll
    for (int t = 0; t < 2; t++) {
        float w0 = g_wsum[t * MM + 0] / (float)N;
        float w1 = g_wsum[t * MM + 1] / (float)N;
        float mx = fmaxf(w0, w1);
        float e0 = expf(w0 - mx), e1 = expf(w1 - mx);
        float s = e0 + e1;
        g_beta[t * MM + 0] = e0 / s;
        g_beta[t * MM + 1] = e1 / s;
    }
}

// ---------------- stage 6: combine + project + relu + layernorm -------------
// grid: (N/32, 2)  block: 256  (4 nodes per warp)
__global__ void k_project(const float* __restrict__ WpU, const float* __restrict__ bpU,
                          const float* __restrict__ WpI, const float* __restrict__ bpI,
                          const float* __restrict__ gln, const float* __restrict__ bln,
                          int N)
{
    __shared__ float Ws[DD * DD];
    __shared__ float bps[DD], gs[DD], bls[DD];
    __shared__ float bet[2];
    const int t   = blockIdx.y;
    const int tid = threadIdx.x;
    const float* Wp = t ? WpI : WpU;
    const float* bp = t ? bpI : bpU;
    for (int i = tid; i < DD * DD; i += blockDim.x) Ws[i] = Wp[i];
    if (tid < DD) { bps[tid] = bp[tid]; gs[tid] = gln[tid]; bls[tid] = bln[tid]; }
    if (tid < 2) bet[tid] = g_beta[t * MM + tid];
    __syncthreads();

    const int warp = tid >> 5, lane = tid & 31;
    const int n0 = (blockIdx.x * 8 + warp) * 4;
    if (n0 >= N) return;

    float c0[4], c1[4], a0[4], a1[4];
#pragma unroll
    for (int j = 0; j < 4; j++) {
        const size_t b0 = ((size_t)(t * MM + 0) * N + n0 + j) * DD;
        const size_t b1 = ((size_t)(t * MM + 1) * N + n0 + j) * DD;
        c0[j] = bet[0] * g_z[b0 + lane]      + bet[1] * g_z[b1 + lane];
        c1[j] = bet[0] * g_z[b0 + 32 + lane] + bet[1] * g_z[b1 + 32 + lane];
        a0[j] = bps[lane]; a1[j] = bps[32 + lane];
    }
#pragma unroll
    for (int k = 0; k < 32; k++) {
        const float w0 = Ws[k * DD + lane];
        const float w1 = Ws[k * DD + 32 + lane];
#pragma unroll
        for (int j = 0; j < 4; j++) {
            float ck = __shfl_sync(0xffffffffu, c0[j], k);
            a0[j] = fmaf(ck, w0, a0[j]);
            a1[j] = fmaf(ck, w1, a1[j]);
        }
    }
#pragma unroll
    for (int k = 0; k < 32; k++) {
        const float w0 = Ws[(k + 32) * DD + lane];
        const float w1 = Ws[(k + 32) * DD + 32 + lane];
#pragma unroll
        for (int j = 0; j < 4; j++) {
            float ck = __shfl_sync(0xffffffffu, c1[j], k);
            a0[j] = fmaf(ck, w0, a0[j]);
            a1[j] = fmaf(ck, w1, a1[j]);
        }
    }
    float* emb = t ? g_embI : g_embU;
#pragma unroll
    for (int j = 0; j < 4; j++) {
        float x0 = fmaxf(a0[j], 0.0f);
        float x1 = fmaxf(a1[j], 0.0f);
        float s = x0 + x1;
#pragma unroll
        for (int o = 16; o > 0; o >>= 1) s += __shfl_xor_sync(0xffffffffu, s, o);
        float mu = s * (1.0f / DD);
        float d0 = x0 - mu, d1 = x1 - mu;
        float v = d0 * d0 + d1 * d1;
#pragma unroll
        for (int o = 16; o > 0; o >>= 1) v += __shfl_xor_sync(0xffffffffu, v, o);
        float inv = rsqrtf(v * (1.0f / DD) + 1e-5f);
        emb[(size_t)(n0 + j) * DD + lane]      = gs[lane]      * d0 * inv + bls[lane];
        emb[(size_t)(n0 + j) * DD + 32 + lane] = gs[32 + lane] * d1 * inv + bls[32 + lane];
    }
}

// ---------------- stage 7: gather outputs -----------------------------------
__global__ void k_gather(const int* __restrict__ ui, const int* __restrict__ ii,
                         const int* __restrict__ ni, float* __restrict__ out)
{
    const int idx = blockIdx.x * blockDim.x + threadIdx.x;
    const int r = idx >> 4, g = idx & 15;
    if (r >= 3 * BB) return;
    const float* srcp;
    if (r < BB)            srcp = &g_embU[(size_t)ui[r] * DD];
    else if (r < 2 * BB)   srcp = &g_embI[(size_t)ii[r - BB] * DD];
    else                   srcp = &g_embI[(size_t)ni[r - 2 * BB] * DD];
    ((float4*)out)[(size_t)r * 16 + g] = ((const float4*)srcp)[g];
}

// ---------------- launch -----------------------------------------------------
extern "C" void kernel_launch(void* const* d_in, const int* in_sizes, int n_in,
                              void* d_out, int out_size)
{
    const int*   user_idx  = (const int*)  d_in[0];
    const int*   item_idx  = (const int*)  d_in[1];
    const int*   neg_idx   = (const int*)  d_in[2];
    const float* user_feat = (const float*)d_in[3];
    const float* item_feat = (const float*)d_in[4];
    const int*   u_src = (const int*)d_in[5];
    const int*   u_dst = (const int*)d_in[6];
    const int*   i_src = (const int*)d_in[7];
    const int*   i_dst = (const int*)d_in[8];
    const float* u_W  = (const float*)d_in[9];
    const float* u_al = (const float*)d_in[10];
    const float* u_ar = (const float*)d_in[11];
    const float* u_b  = (const float*)d_in[12];
    const float* i_W  = (const float*)d_in[13];
    const float* i_al = (const float*)d_in[14];
    const float* i_ar = (const float*)d_in[15];
    const float* i_b  = (const float*)d_in[16];
    const float* u_saW1 = (const float*)d_in[17];
    const float* u_sab1 = (const float*)d_in[18];
    const float* u_saW2 = (const float*)d_in[19];
    const float* i_saW1 = (const float*)d_in[20];
    const float* i_sab1 = (const float*)d_in[21];
    const float* i_saW2 = (const float*)d_in[22];
    const float* userW = (const float*)d_in[23];
    const float* userb = (const float*)d_in[24];
    const float* itemW = (const float*)d_in[25];
    const float* itemb = (const float*)d_in[26];
    const float* ln_g  = (const float*)d_in[27];
    const float* ln_b  = (const float*)d_in[28];
    float* out = (float*)d_out;

    const dim3 blk(256);
    const dim3 gNode((NN + 31) / 32, MM, 2);
    const dim3 gEdge((EE + 255) / 256, MM, 2);
    const dim3 gScat((EE * 16 + 255) / 256, MM, 2);
    const dim3 gProj((NN + 31) / 32, 2);

    k_transform<<<gNode, blk>>>(user_feat, item_feat, u_W, i_W,
                                u_al, i_al, u_ar, i_ar, NN);
    k_edge<<<gEdge, blk>>>(u_src, u_dst, i_src, i_dst, NN);
    k_scatter<<<gScat, blk>>>(u_src, u_dst, i_src, i_dst, NN);
    k_finalize<<<gNode, blk>>>(u_b, i_b, u_saW1, i_saW1,
                               u_sab1, i_sab1, u_saW2, i_saW2, NN);
    k_beta<<<1, 1>>>(NN);
    k_project<<<gProj, blk>>>(userW, userb, itemW, itemb, ln_g, ln_b, NN);
    k_gather<<<(3 * BB * 16 + 255) / 256, blk>>>(user_idx, item_idx, neg_idx, out);
}

// round 15
// speedup vs baseline: 3.0972x; 1.0273x over previous
#include <cuda_runtime.h>

#define NN 100000
#define EE 500000
#define MM 2
#define DD 64
#define HH 128
#define BB 8192

// ---------------- scratch (static __device__ per allocation rules) ----------
// ntype-major: index = ((t*MM + m)*NN + n)
__device__ float g_feat[2 * MM * NN * DD];   // transformed features
__device__ float g_z[2 * MM * NN * DD];      // unnormalized accumulator, then elu'd z
__device__ float g_el[2 * MM * NN];
__device__ float g_er[2 * MM * NN];
__device__ float g_den[2 * MM * NN];         // softmax denominators
__device__ float g_embU[NN * DD];
__device__ float g_embI[NN * DD];
__device__ float g_wsum[2 * MM];

__device__ __forceinline__ float tanh_fast(float x) {
    float y;
    asm("tanh.approx.f32 %0, %1;" : "=f"(y) : "f"(x));
    return y;
}

// ---------------- stage 1: feat = h @ W[m]; el, er; init accumulators -------
// grid: (N/32, MM, 2)  block: 256  (8 warps x 4 nodes = 32 nodes/block)
__global__ void k_transform(const float* __restrict__ hU, const float* __restrict__ hI,
                            const float* __restrict__ WU, const float* __restrict__ WI,
                            const float* __restrict__ alU, const float* __restrict__ alI,
                            const float* __restrict__ arU, const float* __restrict__ arI,
                            int N)
{
    __shared__ float Ws[DD * DD];
    __shared__ float als[DD], ars[DD];
    const int t   = blockIdx.z;
    const int m   = blockIdx.y;
    const int tid = threadIdx.x;
    const float* h  = t ? hI  : hU;
    const float* W  = t ? WI  : WU;
    const float* al = t ? alI : alU;
    const float* ar = t ? arI : arU;
    for (int i = tid; i < DD * DD; i += blockDim.x) Ws[i] = W[m * DD * DD + i];
    if (tid < DD) { als[tid] = al[m * DD + tid]; ars[tid] = ar[m * DD + tid]; }
    if (blockIdx.x == 0 && m == 0 && tid < MM) g_wsum[t * MM + tid] = 0.0f;
    __syncthreads();

    const int warp = tid >> 5, lane = tid & 31;
    const int n0 = (blockIdx.x * 8 + warp) * 4;          // 4 nodes per warp
    if (n0 >= N) return;

    float hr0[4], hr1[4], a0[4], a1[4];
#pragma unroll
    for (int j = 0; j < 4; j++) {
        hr0[j] = h[(n0 + j) * DD + lane];
        hr1[j] = h[(n0 + j) * DD + 32 + lane];
        a0[j] = 0.0f; a1[j] = 0.0f;
    }
#pragma unroll
    for (int k = 0; k < 32; k++) {
        const float w0 = Ws[k * DD + lane];
        const float w1 = Ws[k * DD + 32 + lane];
#pragma unroll
        for (int j = 0; j < 4; j++) {
            float hk = __shfl_sync(0xffffffffu, hr0[j], k);
            a0[j] = fmaf(hk, w0, a0[j]);
            a1[j] = fmaf(hk, w1, a1[j]);
        }
    }
#pragma unroll
    for (int k = 0; k < 32; k++) {
        const float w0 = Ws[(k + 32) * DD + lane];
        const float w1 = Ws[(k + 32) * DD + 32 + lane];
#pragma unroll
        for (int j = 0; j < 4; j++) {
            float hk = __shfl_sync(0xffffffffu, hr1[j], k);
            a0[j] = fmaf(hk, w0, a0[j]);
            a1[j] = fmaf(hk, w1, a1[j]);
        }
    }
    const size_t nbase = (size_t)(t * MM + m) * N;
    float pe[4], pr[4];
#pragma unroll
    for (int j = 0; j < 4; j++) {
        const size_t base = (nbase + n0 + j) * DD;
        g_feat[base + lane]      = a0[j];
        g_feat[base + 32 + lane] = a1[j];
        g_z[base + lane]      = 0.0f;
        g_z[base + 32 + lane] = 0.0f;
        pe[j] = a0[j] * als[lane] + a1[j] * als[32 + lane];
        pr[j] = a0[j] * ars[lane] + a1[j] * ars[32 + lane];
#pragma unroll
        for (int o = 16; o > 0; o >>= 1) {
            pe[j] += __shfl_xor_sync(0xffffffffu, pe[j], o);
            pr[j] += __shfl_xor_sync(0xffffffffu, pr[j], o);
        }
    }
    if (lane == 0) {
#pragma unroll
        for (int j = 0; j < 4; j++) {
            g_el[nbase + n0 + j]  = pe[j];
            g_er[nbase + n0 + j]  = pr[j];
            g_den[nbase + n0 + j] = 0.0f;
        }
    }
}

// ------- stage 2 (fused): edge logit + exp + den + UNNORMALIZED scatter -----
// Softmax identity: sum_e alpha_e*feat = (sum_e ex_e*feat)/(den + 1e-9), den
// per-dst. So we scatter ex*feat directly and divide once per node later.
// No max subtraction: logits bounded << 80, exp cannot overflow.
// grid: (E*16/256, MM, 2); 16 threads per edge; leader computes scalars once
__global__ void k_edge_scatter(const int* __restrict__ srcU, const int* __restrict__ dstU,
                               const int* __restrict__ srcI, const int* __restrict__ dstI,
                               int N)
{
    const int t   = blockIdx.z;
    const int m   = blockIdx.y;
    const int idx = blockIdx.x * blockDim.x + threadIdx.x;
    const int e = idx >> 4;
    const int g = idx & 15;
    if (e >= EE) return;
    const int lane = threadIdx.x & 31;
    const int lead = lane & 16;                      // leader lane of 16-group
    const unsigned mask = 0xFFFFu << lead;

    const size_t nbase = (size_t)(t * MM + m) * N;
    int s = 0, d = 0;
    float ex = 0.0f;
    if (g == 0) {
        const int* src = t ? srcI : srcU;
        const int* dst = t ? dstI : dstU;
        s = src[m * EE + e];
        d = dst[m * EE + e];
        float v = g_el[nbase + s] + g_er[nbase + d];
        v = (v > 0.0f) ? v : 0.2f * v;   // leaky relu, slope 0.2
        ex = __expf(v);
        atomicAdd(&g_den[nbase + d], ex);
    }
    s  = __shfl_sync(mask, s, lead);
    d  = __shfl_sync(mask, d, lead);
    ex = __shfl_sync(mask, ex, lead);

    const float4* f4 = (const float4*)&g_feat[(nbase + s) * DD];
    float4 v = f4[g];
    v.x *= ex; v.y *= ex; v.z *= ex; v.w *= ex;
    float* p = &g_z[(nbase + d) * DD + g * 4];
    asm volatile("red.global.add.v4.f32 [%0], {%1,%2,%3,%4};"
                 :: "l"(p), "f"(v.x), "f"(v.y), "f"(v.z), "f"(v.w) : "memory");
}

// ---------------- stage 3: z = elu(acc/den + b); semantic score -------------
// grid: (N/32, MM, 2)  block: 256  (4 nodes per warp)
__global__ void k_finalize(const float* __restrict__ bU, const float* __restrict__ bI,
                           const float* __restrict__ W1U, const float* __restrict__ W1I,
                           const float* __restrict__ b1U, const float* __restrict__ b1I,
                           const float* __restrict__ W2U, const float* __restrict__ W2I,
                           int N)
{
    __shared__ float W1s[DD * HH];
    __shared__ float b1s[HH], W2s[HH], bs[DD];
    __shared__ float part[8];
    const int t   = blockIdx.z;
    const int m   = blockIdx.y;
    const int tid = threadIdx.x;
    const float* b  = t ? bI  : bU;
    const float* W1 = t ? W1I : W1U;
    const float* b1 = t ? b1I : b1U;
    const float* W2 = t ? W2I : W2U;
    for (int i = tid; i < DD * HH; i += blockDim.x) W1s[i] = W1[i];
    if (tid < HH) { b1s[tid] = b1[tid]; W2s[tid] = W2[tid]; }
    if (tid < DD) bs[tid] = b[m * DD + tid];
    __syncthreads();

    const int warp = tid >> 5, lane = tid & 31;
    const int n0 = (blockIdx.x * 8 + warp) * 4;
    float sval = 0.0f;
    if (n0 < N) {
        const size_t nbase = (size_t)(t * MM + m) * N;
        float z0[4], z1[4];
#pragma unroll
        for (int j = 0; j < 4; j++) {
            const size_t base = (nbase + n0 + j) * DD;
            const float invden = 1.0f / (g_den[nbase + n0 + j] + 1e-9f);
            float u0 = g_z[base + lane]      * invden + bs[lane];
            float u1 = g_z[base + 32 + lane] * invden + bs[32 + lane];
            u0 = (u0 > 0.0f) ? u0 : expm1f(u0);   // elu, alpha=1
            u1 = (u1 > 0.0f) ? u1 : expm1f(u1);
            g_z[base + lane]      = u0;
            g_z[base + 32 + lane] = u1;
            z0[j] = u0; z1[j] = u1;
        }
        float acc[4][4];
#pragma unroll
        for (int j = 0; j < 4; j++)
#pragma unroll
            for (int c = 0; c < 4; c++) acc[j][c] = b1s[lane + 32 * c];
#pragma unroll
        for (int k = 0; k < 32; k++) {
            float w[4];
#pragma unroll
            for (int c = 0; c < 4; c++) w[c] = W1s[k * HH + lane + 32 * c];
#pragma unroll
            for (int j = 0; j < 4; j++) {
                float zk = __shfl_sync(0xffffffffu, z0[j], k);
#pragma unroll
                for (int c = 0; c < 4; c++) acc[j][c] = fmaf(zk, w[c], acc[j][c]);
            }
        }
#pragma unroll
        for (int k = 0; k < 32; k++) {
            float w[4];
#pragma unroll
            for (int c = 0; c < 4; c++) w[c] = W1s[(k + 32) * HH + lane + 32 * c];
#pragma unroll
            for (int j = 0; j < 4; j++) {
                float zk = __shfl_sync(0xffffffffu, z1[j], k);
#pragma unroll
                for (int c = 0; c < 4; c++) acc[j][c] = fmaf(zk, w[c], acc[j][c]);
            }
        }
        // only the SUM over nodes of the per-node score is needed downstream
#pragma unroll
        for (int j = 0; j < 4; j++)
#pragma unroll
            for (int c = 0; c < 4; c++)
                sval += tanh_fast(acc[j][c]) * W2s[lane + 32 * c];
#pragma unroll
        for (int o = 16; o > 0; o >>= 1) sval += __shfl_xor_sync(0xffffffffu, sval, o);
    }
    if (lane == 0) part[warp] = (n0 < N) ? sval : 0.0f;
    __syncthreads();
    if (tid == 0) {
        float v = 0.0f;
#pragma unroll
        for (int w = 0; w < 8; w++) v += part[w];
        atomicAdd(&g_wsum[t * MM + m], v);
    }
}

// ---------------- stage 4: combine + project + relu + layernorm -------------
// (beta softmax over metapaths computed per-block from g_wsum — deterministic)
// grid: (N/32, 2)  block: 256  (4 nodes per warp)
__global__ void k_project(const float* __restrict__ WpU, const float* __restrict__ bpU,
                          const float* __restrict__ WpI, const float* __restrict__ bpI,
                          const float* __restrict__ gln, const float* __restrict__ bln,
                          int N)
{
    __shared__ float Ws[DD * DD];
    __shared__ float bps[DD], gs[DD], bls[DD];
    __shared__ float bet[2];
    const int t   = blockIdx.y;
    const int tid = threadIdx.x;
    const float* Wp = t ? WpI : WpU;
    const float* bp = t ? bpI : bpU;
    for (int i = tid; i < DD * DD; i += blockDim.x) Ws[i] = Wp[i];
    if (tid < DD) { bps[tid] = bp[tid]; gs[tid] = gln[tid]; bls[tid] = bln[tid]; }
    if (tid == 0) {
        float w0 = g_wsum[t * MM + 0] / (float)N;
        float w1 = g_wsum[t * MM + 1] / (float)N;
        float mx = fmaxf(w0, w1);
        float e0 = expf(w0 - mx), e1 = expf(w1 - mx);
        float s = e0 + e1;
        bet[0] = e0 / s;
        bet[1] = e1 / s;
    }
    __syncthreads();

    const int warp = tid >> 5, lane = tid & 31;
    const int n0 = (blockIdx.x * 8 + warp) * 4;
    if (n0 >= N) return;

    float c0[4], c1[4], a0[4], a1[4];
#pragma unroll
    for (int j = 0; j < 4; j++) {
        const size_t b0 = ((size_t)(t * MM + 0) * N + n0 + j) * DD;
        const size_t b1 = ((size_t)(t * MM + 1) * N + n0 + j) * DD;
        c0[j] = bet[0] * g_z[b0 + lane]      + bet[1] * g_z[b1 + lane];
        c1[j] = bet[0] * g_z[b0 + 32 + lane] + bet[1] * g_z[b1 + 32 + lane];
        a0[j] = bps[lane]; a1[j] = bps[32 + lane];
    }
#pragma unroll
    for (int k = 0; k < 32; k++) {
        const float w0 = Ws[k * DD + lane];
        const float w1 = Ws[k * DD + 32 + lane];
#pragma unroll
        for (int j = 0; j < 4; j++) {
            float ck = __shfl_sync(0xffffffffu, c0[j], k);
            a0[j] = fmaf(ck, w0, a0[j]);
            a1[j] = fmaf(ck, w1, a1[j]);
        }
    }
#pragma unroll
    for (int k = 0; k < 32; k++) {
        const float w0 = Ws[(k + 32) * DD + lane];
        const float w1 = Ws[(k + 32) * DD + 32 + lane];
#pragma unroll
        for (int j = 0; j < 4; j++) {
            float ck = __shfl_sync(0xffffffffu, c1[j], k);
            a0[j] = fmaf(ck, w0, a0[j]);
            a1[j] = fmaf(ck, w1, a1[j]);
        }
    }
    float* emb = t ? g_embI : g_embU;
#pragma unroll
    for (int j = 0; j < 4; j++) {
        float x0 = fmaxf(a0[j], 0.0f);
        float x1 = fmaxf(a1[j], 0.0f);
        float s = x0 + x1;
#pragma unroll
        for (int o = 16; o > 0; o >>= 1) s += __shfl_xor_sync(0xffffffffu, s, o);
        float mu = s * (1.0f / DD);
        float d0 = x0 - mu, d1 = x1 - mu;
        float v = d0 * d0 + d1 * d1;
#pragma unroll
        for (int o = 16; o > 0; o >>= 1) v += __shfl_xor_sync(0xffffffffu, v, o);
        float inv = rsqrtf(v * (1.0f / DD) + 1e-5f);
        emb[(size_t)(n0 + j) * DD + lane]      = gs[lane]      * d0 * inv + bls[lane];
        emb[(size_t)(n0 + j) * DD + 32 + lane] = gs[32 + lane] * d1 * inv + bls[32 + lane];
    }
}

// ---------------- stage 5: gather outputs -----------------------------------
__global__ void k_gather(const int* __restrict__ ui, const int* __restrict__ ii,
                         const int* __restrict__ ni, float* __restrict__ out)
{
    const int idx = blockIdx.x * blockDim.x + threadIdx.x;
    const int r = idx >> 4, g = idx & 15;
    if (r >= 3 * BB) return;
    const float* srcp;
    if (r < BB)            srcp = &g_embU[(size_t)ui[r] * DD];
    else if (r < 2 * BB)   srcp = &g_embI[(size_t)ii[r - BB] * DD];
    else                   srcp = &g_embI[(size_t)ni[r - 2 * BB] * DD];
    ((float4*)out)[(size_t)r * 16 + g] = ((const float4*)srcp)[g];
}

// ---------------- launch -----------------------------------------------------
extern "C" void kernel_launch(void* const* d_in, const int* in_sizes, int n_in,
                              void* d_out, int out_size)
{
    const int*   user_idx  = (const int*)  d_in[0];
    const int*   item_idx  = (const int*)  d_in[1];
    const int*   neg_idx   = (const int*)  d_in[2];
    const float* user_feat = (const float*)d_in[3];
    const float* item_feat = (const float*)d_in[4];
    const int*   u_src = (const int*)d_in[5];
    const int*   u_dst = (const int*)d_in[6];
    const int*   i_src = (const int*)d_in[7];
    const int*   i_dst = (const int*)d_in[8];
    const float* u_W  = (const float*)d_in[9];
    const float* u_al = (const float*)d_in[10];
    const float* u_ar = (const float*)d_in[11];
    const float* u_b  = (const float*)d_in[12];
    const float* i_W  = (const float*)d_in[13];
    const float* i_al = (const float*)d_in[14];
    const float* i_ar = (const float*)d_in[15];
    const float* i_b  = (const float*)d_in[16];
    const float* u_saW1 = (const float*)d_in[17];
    const float* u_sab1 = (const float*)d_in[18];
    const float* u_saW2 = (const float*)d_in[19];
    const float* i_saW1 = (const float*)d_in[20];
    const float* i_sab1 = (const float*)d_in[21];
    const float* i_saW2 = (const float*)d_in[22];
    const float* userW = (const float*)d_in[23];
    const float* userb = (const float*)d_in[24];
    const float* itemW = (const float*)d_in[25];
    const float* itemb = (const float*)d_in[26];
    const float* ln_g  = (const float*)d_in[27];
    const float* ln_b  = (const float*)d_in[28];
    float* out = (float*)d_out;

    const dim3 blk(256);
    const dim3 gNode((NN + 31) / 32, MM, 2);
    const dim3 gScat((EE * 16 + 255) / 256, MM, 2);
    const dim3 gProj((NN + 31) / 32, 2);

    k_transform<<<gNode, blk>>>(user_feat, item_feat, u_W, i_W,
                                u_al, i_al, u_ar, i_ar, NN);
    k_edge_scatter<<<gScat, blk>>>(u_src, u_dst, i_src, i_dst, NN);
    k_finalize<<<gNode, blk>>>(u_b, i_b, u_saW1, i_saW1,
                               u_sab1, i_sab1, u_saW2, i_saW2, NN);
    k_project<<<gProj, blk>>>(userW, userb, itemW, itemb, ln_g, ln_b, NN);
    k_gather<<<(3 * BB * 16 + 255) / 256, blk>>>(user_idx, item_idx, neg_idx, out);
}